// round 14
// baseline (speedup 1.0000x reference)
#include <cuda_runtime.h>
#include <cuda_fp16.h>
#include <cstdint>
#include <cstring>

#define B_ 8
#define T_ 256
#define H_ 1024
#define V_ 32000
#define M_ (B_*T_)          // 2048 rows = (b,t)

// ---------------- scratch (device globals; no allocation allowed) ----------
__device__ __align__(16) __half g_Ahi[M_*H_];            // emb hi
__device__ __align__(16) __half g_Alo[M_*H_];            // emb lo
__device__ __align__(16) __half g_Wih[H_*H_];            // W_ih fp16
__device__ __align__(16) __half g_Wo[(size_t)V_*H_];     // W_out fp16
__device__ __align__(16) __half g_Hh[M_*H_];             // hs fp16
__device__ __align__(16) float g_pre[M_*H_];   // x_t @ W_ih^T + b_ih + b_hh
__device__ __align__(16) float g_hs [M_*H_];   // hidden states [b][t][j]
__device__ __align__(16) float g_h  [2*B_*H_]; // double-buffered current h
__device__ float g_bsum[H_];
__device__ unsigned g_bar_count;

// ---------------- PTX helpers (arch-neutral: ldmatrix/mma/cp.async) --------
__device__ __forceinline__ uint32_t smem_to_u32(const void* p) {
    uint32_t a;
    asm("{ .reg .u64 t; cvta.to.shared.u64 t, %1; cvt.u32.u64 %0, t; }"
        : "=r"(a) : "l"(p));
    return a;
}
__device__ __forceinline__ void ldsm_x4(uint32_t* r, uint32_t addr) {
    asm volatile("ldmatrix.sync.aligned.m8n8.x4.shared.b16 {%0,%1,%2,%3}, [%4];"
        : "=r"(r[0]), "=r"(r[1]), "=r"(r[2]), "=r"(r[3]) : "r"(addr));
}
__device__ __forceinline__ void mma_f16(float* d, const uint32_t* a, const uint32_t* b) {
    asm volatile(
        "mma.sync.aligned.m16n8k16.row.col.f32.f16.f16.f32 "
        "{%0,%1,%2,%3}, {%4,%5,%6,%7}, {%8,%9}, {%0,%1,%2,%3};"
        : "+f"(d[0]), "+f"(d[1]), "+f"(d[2]), "+f"(d[3])
        : "r"(a[0]), "r"(a[1]), "r"(a[2]), "r"(a[3]), "r"(b[0]), "r"(b[1]));
}
__device__ __forceinline__ void cp16(uint32_t saddr, const void* g) {
    asm volatile("cp.async.cg.shared.global [%0], [%1], 16;" :: "r"(saddr), "l"(g));
}
#define CP_COMMIT() asm volatile("cp.async.commit_group;" ::: "memory")
#define CP_WAIT0()  asm volatile("cp.async.wait_group 0;" ::: "memory")
#define CP_WAIT1()  asm volatile("cp.async.wait_group 1;" ::: "memory")

// packed fp32x2 FMA (verified working on this toolchain)
__device__ __forceinline__ void ffma2(unsigned long long &c,
                                      unsigned long long a,
                                      unsigned long long b) {
    asm("fma.rn.f32x2 %0, %1, %2, %0;" : "+l"(c) : "l"(a), "l"(b));
}
__device__ __forceinline__ unsigned long long pk2(float x, float y) {
    float2 t; t.x = x; t.y = y;
    unsigned long long r; memcpy(&r, &t, 8); return r;
}
__device__ __forceinline__ float upk_sum(unsigned long long v) {
    float2 t; memcpy(&t, &v, 8); return t.x + t.y;
}

// ---------------- gather: emb rows split to fp16 hi/lo + fused bias --------
__global__ void gather_kernel(const int* __restrict__ x,
                              const float* __restrict__ embed,
                              const float* __restrict__ b_ih,
                              const float* __restrict__ b_hh) {
    int m = blockIdx.x;
    if (m < M_) {
        int tok = x[m];
        for (int i = threadIdx.x; i < H_; i += blockDim.x) {
            float v = embed[(size_t)tok * H_ + i];
            __half h = __float2half_rn(v);
            g_Ahi[(size_t)m * H_ + i] = h;
            g_Alo[(size_t)m * H_ + i] = __float2half_rn(v - __half2float(h));
        }
    } else {
        // also reset the scan's monotonic grid-barrier counter (stream order
        // guarantees this lands before scan_kernel starts, every replay)
        if (threadIdx.x == 0) g_bar_count = 0;
        for (int i = threadIdx.x; i < H_; i += blockDim.x)
            g_bsum[i] = b_ih[i] + b_hh[i];
    }
}

// ---------------- fp32 -> fp16 (round-to-nearest) --------------------------
__global__ void conv_h_kernel(const float* __restrict__ src,
                              __half* __restrict__ dst, size_t n) {
    size_t i = ((size_t)blockIdx.x * blockDim.x + threadIdx.x) * 4;
    if (i < n) {
        float4 v = *reinterpret_cast<const float4*>(src + i);
        __half2 a = {__float2half_rn(v.x), __float2half_rn(v.y)};
        __half2 b = {__float2half_rn(v.z), __float2half_rn(v.w)};
        *reinterpret_cast<__half2*>(dst + i)     = a;
        *reinterpret_cast<__half2*>(dst + i + 2) = b;
    }
}

// ---------------- fp16 HMMA GEMM, templated pass count ---------------------
// NPASS=2: C = (Ahi+Alo)*B + bias (A exact as fp16 pair)
// NPASS=1: C = Ahi*B + bias       (pure fp16 operands)
// A: [Mrows][H_] row-major, B: [Ncols][H_] row-major.  K = H_ = 1024 fixed.
#define GBM 128
#define GBN 128
#define GBK 32
#define NKC (H_/GBK)                    // 32 k-chunks
#define LDT 40                          // smem row stride in fp16 (pad 8)
#define MAT_B (GBM*LDT*2)               // 10240 bytes per matrix tile

template<int NPASS>
__global__ __launch_bounds__(256, 2)
void gemm_mma(const __half* __restrict__ Ahi, const __half* __restrict__ Alo,
              const __half* __restrict__ Bh,
              const float* __restrict__ bias, float* __restrict__ C, int Ndim) {
    constexpr int BSLOT   = NPASS;              // B tile slot index
    constexpr int STAGE_B = (NPASS + 1) * MAT_B;
    extern __shared__ __align__(16) char sm[];
    const uint32_t sb = smem_to_u32(sm);
    const int tid  = threadIdx.x;
    const int lane = tid & 31, wid = tid >> 5;
    const int wm = wid & 3, wn = wid >> 2;      // warp tile: rows 32*wm, cols 64*wn
    const int bm = blockIdx.x, bn = blockIdx.y;

    // ---- prefetch chunk c into stage c&1 ----
    auto prefetch = [&](int c) {
        const uint32_t st = sb + (uint32_t)(c & 1) * STAGE_B;
        const int kcol = c * GBK;
        #pragma unroll
        for (int q = 0; q < 2; q++) {
            const int u = tid + 256*q;
            const int r = u >> 2, sg = u & 3;
            const uint32_t so = (uint32_t)(r*LDT + sg*8) * 2;
            const size_t goA = (size_t)(bm*GBM + r) * H_ + kcol + sg*8;
            const size_t goB = (size_t)(bn*GBN + r) * H_ + kcol + sg*8;
            cp16(st + 0*MAT_B + so, Ahi + goA);
            if (NPASS == 2) cp16(st + 1*MAT_B + so, Alo + goA);
            cp16(st + BSLOT*MAT_B + so, Bh + goB);
        }
    };

    float acc[2][8][4];
    #pragma unroll
    for (int i = 0; i < 2; i++)
        #pragma unroll
        for (int j = 0; j < 8; j++)
            #pragma unroll
            for (int q = 0; q < 4; q++) acc[i][j][q] = 0.f;

    prefetch(0); CP_COMMIT();

    for (int c = 0; c < NKC; c++) {
        if (c + 1 < NKC) { prefetch(c + 1); CP_COMMIT(); CP_WAIT1(); }
        else             { CP_WAIT0(); }
        __syncthreads();

        const uint32_t st = sb + (uint32_t)(c & 1) * STAGE_B;
        #pragma unroll
        for (int ks = 0; ks < 2; ks++) {
            // A fragments: rows wm*32 + f*16 + lane%16
            uint32_t ah[8], al[8];
            #pragma unroll
            for (int f = 0; f < 2; f++) {
                const int row = wm*32 + f*16 + (lane & 15);
                const uint32_t off = (uint32_t)(row*LDT + ks*16 + (lane >> 4)*8) * 2;
                ldsm_x4(ah + 4*f, st + 0*MAT_B + off);
                if (NPASS == 2) ldsm_x4(al + 4*f, st + 1*MAT_B + off);
            }
            // B fragments
            uint32_t bb[16];
            #pragma unroll
            for (int p = 0; p < 4; p++) {
                const int n  = wn*64 + p*16 + ((lane >> 4) << 3) + (lane & 7);
                const int kc = ks*16 + ((lane >> 3) & 1) * 8;
                const uint32_t off = (uint32_t)(n*LDT + kc) * 2;
                ldsm_x4(bb + 4*p, st + BSLOT*MAT_B + off);
            }
            // pass 1: Ahi * B
            #pragma unroll
            for (int fm = 0; fm < 2; fm++)
                #pragma unroll
                for (int fn = 0; fn < 8; fn++)
                    mma_f16(acc[fm][fn], ah + 4*fm, bb + 2*fn);
            // pass 2: Alo * B
            if (NPASS == 2) {
                #pragma unroll
                for (int fm = 0; fm < 2; fm++)
                    #pragma unroll
                    for (int fn = 0; fn < 8; fn++)
                        mma_f16(acc[fm][fn], al + 4*fm, bb + 2*fn);
            }
        }
        __syncthreads();
    }

    // ---- epilogue: acc + bias -> C ----
    #pragma unroll
    for (int fm = 0; fm < 2; fm++) {
        const int row = bm*GBM + wm*32 + fm*16 + (lane >> 2);
        #pragma unroll
        for (int fn = 0; fn < 8; fn++) {
            const int col = bn*GBN + wn*64 + fn*8 + (lane & 3)*2;
            const float2 bv = *reinterpret_cast<const float2*>(bias + col);
            float2 o0, o1;
            o0.x = acc[fm][fn][0] + bv.x; o0.y = acc[fm][fn][1] + bv.y;
            o1.x = acc[fm][fn][2] + bv.x; o1.y = acc[fm][fn][3] + bv.y;
            *reinterpret_cast<float2*>(C + (size_t)row     * Ndim + col) = o0;
            *reinterpret_cast<float2*>(C + (size_t)(row+8) * Ndim + col) = o1;
        }
    }
}

// ---------------- persistent scan: 128 CTAs x 128 thr, 2 cols/warp ---------
// Grid barrier: monotonic counter, RED arrival, hot volatile poll, single
// release fence per CTA per step. h cross-step traffic is L1-bypassing
// (__stcg / __ldcg), so no acquire-side L1 invalidate is needed.
#define SCAN_BLOCKS 128
#define SCAN_THREADS 128

__device__ __forceinline__ void grid_barrier_t(unsigned target) {
    __syncthreads();
    if (threadIdx.x == 0) {
        __threadfence();                       // release: publish h writes to L2
        atomicAdd(&g_bar_count, 1);            // result unused -> REDG
        const volatile unsigned* c = (const volatile unsigned*)&g_bar_count;
        while (*c < target) { }                // hot poll (L2)
    }
    __syncthreads();                            // exec+compiler barrier for CTA
}

__global__ __launch_bounds__(SCAN_THREADS)
void scan_kernel(const float* __restrict__ Whh, float* __restrict__ hfinal) {
    __shared__ __align__(16) float hsh[B_*H_];   // 32 KB
    const int tid  = threadIdx.x;
    const int warp = tid >> 5;                   // 0..3
    const int lane = tid & 31;
    const int j0   = blockIdx.x * 8 + warp * 2;  // two adjacent columns per warp
    const int j1   = j0 + 1;

    // Two W_hh rows stay in registers, packed as f32x2 pairs.
    unsigned long long w0[16], w1[16];
    {
        const float4* r0 = reinterpret_cast<const float4*>(Whh + (size_t)j0 * H_);
        const float4* r1 = reinterpret_cast<const float4*>(Whh + (size_t)j1 * H_);
        #pragma unroll
        for (int i = 0; i < 8; i++) {
            float4 a = r0[lane + 32*i];
            float4 b = r1[lane + 32*i];
            w0[2*i]   = pk2(a.x, a.y); w0[2*i+1] = pk2(a.z, a.w);
            w1[2*i]   = pk2(b.x, b.y); w1[2*i+1] = pk2(b.z, b.w);
        }
    }

    // zero h buffer 0 (L2-resident stores)
    {
        int idx = blockIdx.x*SCAN_THREADS + tid;
        if (idx < B_*H_) __stcg(&g_h[idx], 0.f);
    }
    unsigned bar_k = 1;
    grid_barrier_t(bar_k * SCAN_BLOCKS); bar_k++;

    for (int t = 0; t < T_; t++) {
        const int rp = t & 1, wp = rp ^ 1;
        // stage current h into shared, bypassing L1 (coherence point = L2)
        float4* hs4 = reinterpret_cast<float4*>(hsh);
        const float4* hg4 = reinterpret_cast<const float4*>(g_h + rp*B_*H_);
        #pragma unroll
        for (int i = 0; i < (B_*H_/4)/SCAN_THREADS; i++)
            hs4[tid + SCAN_THREADS*i] = __ldcg(&hg4[tid + SCAN_THREADS*i]);
        __syncthreads();

        unsigned long long a0[B_], a1[B_];
        #pragma unroll
        for (int b = 0; b < B_; b++) { a0[b] = 0ull; a1[b] = 0ull; }
        #pragma unroll
        for (int i = 0; i < 8; i++) {
            const unsigned long long wl0 = w0[2*i], wh0 = w0[2*i+1];
            const unsigned long long wl1 = w1[2*i], wh1 = w1[2*i+1];
            #pragma unroll
            for (int b = 0; b < B_; b++) {
                const float4 hv = *reinterpret_cast<const float4*>(&hsh[b*H_ + lane*4 + 128*i]);
                const unsigned long long hl = pk2(hv.x, hv.y);
                const unsigned long long hh = pk2(hv.z, hv.w);
                ffma2(a0[b], wl0, hl); ffma2(a0[b], wh0, hh);
                ffma2(a1[b], wl1, hl); ffma2(a1[b], wh1, hh);
            }
        }
        // butterfly-reduce both column accumulators (all lanes get results)
        float s0[B_], s1[B_];
        #pragma unroll
        for (int b = 0; b < B_; b++) {
            float v0 = upk_sum(a0[b]), v1 = upk_sum(a1[b]);
            #pragma unroll
            for (int off = 16; off; off >>= 1) {
                v0 += __shfl_xor_sync(0xffffffffu, v0, off);
                v1 += __shfl_xor_sync(0xffffffffu, v1, off);
            }
            s0[b] = v0; s1[b] = v1;
        }
        // lanes 0-7 write column j0 (batch=lane); lanes 8-15 write j1
        if (lane < 16) {
            const int b = lane & 7;
            float va = s0[0], vb = s1[0];
            if (b == 1) { va = s0[1]; vb = s1[1]; }
            if (b == 2) { va = s0[2]; vb = s1[2]; }
            if (b == 3) { va = s0[3]; vb = s1[3]; }
            if (b == 4) { va = s0[4]; vb = s1[4]; }
            if (b == 5) { va = s0[5]; vb = s1[5]; }
            if (b == 6) { va = s0[6]; vb = s1[6]; }
            if (b == 7) { va = s0[7]; vb = s1[7]; }
            const float a = (lane < 8) ? va : vb;
            const int   j = (lane < 8) ? j0 : j1;
            const float hn = tanhf(a + g_pre[(size_t)b*(T_*H_) + t*H_ + j]);
            __stcg(&g_h[wp*B_*H_ + b*H_ + j], hn);
            g_hs[(size_t)b*(T_*H_) + t*H_ + j] = hn;
            if (t == T_-1) hfinal[b*H_ + j] = hn;
        }
        grid_barrier_t(bar_k * SCAN_BLOCKS); bar_k++;
    }
}

// ---------------- launch ----------------------------------------------------
extern "C" void kernel_launch(void* const* d_in, const int* in_sizes, int n_in,
                              void* d_out, int out_size) {
    const int*   x     = (const int*)  d_in[0];
    const float* embed = (const float*)d_in[1];
    const float* W_ih  = (const float*)d_in[2];
    const float* b_ih  = (const float*)d_in[3];
    const float* W_hh  = (const float*)d_in[4];
    const float* b_hh  = (const float*)d_in[5];
    const float* W_out = (const float*)d_in[6];
    const float* b_out = (const float*)d_in[7];
    float* out = (float*)d_out;

    void *p_Ahi, *p_Alo, *p_Wih, *p_Wo, *p_Hh, *p_pre, *p_hs, *p_bsum;
    cudaGetSymbolAddress(&p_Ahi, g_Ahi);   cudaGetSymbolAddress(&p_Alo, g_Alo);
    cudaGetSymbolAddress(&p_Wih, g_Wih);   cudaGetSymbolAddress(&p_Wo, g_Wo);
    cudaGetSymbolAddress(&p_Hh, g_Hh);
    cudaGetSymbolAddress(&p_pre, g_pre);   cudaGetSymbolAddress(&p_hs, g_hs);
    cudaGetSymbolAddress(&p_bsum, g_bsum);

    cudaFuncSetAttribute(gemm_mma<2>, cudaFuncAttributeMaxDynamicSharedMemorySize, 3*MAT_B*2);
    cudaFuncSetAttribute(gemm_mma<1>, cudaFuncAttributeMaxDynamicSharedMemorySize, 2*MAT_B*2);

    // 1) gather embeddings (split to fp16 hi/lo) + fused bias + barrier reset
    gather_kernel<<<M_ + 1, 256>>>(x, embed, b_ih, b_hh);

    // 2) convert weights to fp16
    conv_h_kernel<<<(H_*H_/4 + 255)/256, 256>>>(W_ih, (__half*)p_Wih, (size_t)H_*H_);
    conv_h_kernel<<<(int)(((size_t)V_*H_/4 + 255)/256), 256>>>(W_out, (__half*)p_Wo, (size_t)V_*H_);

    // 3) pre = emb @ W_ih^T + (b_ih + b_hh)   [2048 x 1024], exact-A 2-pass
    gemm_mma<2><<<dim3(M_/GBM, H_/GBN), 256, 3*MAT_B*2>>>(
        (const __half*)p_Ahi, (const __half*)p_Alo, (const __half*)p_Wih,
        (const float*)p_bsum, (float*)p_pre, H_);

    // 4) persistent recurrent scan; writes g_hs and h_final tail of d_out
    scan_kernel<<<SCAN_BLOCKS, SCAN_THREADS>>>(W_hh, out + (size_t)M_ * V_);

    // 5) convert hidden states to fp16 (1-pass A operand)
    conv_h_kernel<<<(M_*H_/4 + 255)/256, 256>>>((const float*)p_hs,
        (__half*)p_Hh, (size_t)M_*H_);

    // 6) outputs = hs @ W_out^T + b_out   [2048 x 32000], pure-fp16 1-pass
    gemm_mma<1><<<dim3(M_/GBM, V_/GBN), 256, 2*MAT_B*2>>>(
        (const __half*)p_Hh, (const __half*)nullptr, (const __half*)p_Wo,
        b_out, out, V_);
}

// round 15
// speedup vs baseline: 1.4608x; 1.4608x over previous
#include <cuda_runtime.h>
#include <cuda_fp16.h>
#include <cstdint>
#include <cstring>

#define B_ 8
#define T_ 256
#define H_ 1024
#define V_ 32000
#define M_ (B_*T_)          // 2048 rows = (b,t)

// ---------------- scratch (device globals; no allocation allowed) ----------
__device__ __align__(16) __half g_Ahi[M_*H_];            // emb hi
__device__ __align__(16) __half g_Alo[M_*H_];            // emb lo
__device__ __align__(16) __half g_Wih[H_*H_];            // W_ih fp16
__device__ __align__(16) __half g_Wo[(size_t)V_*H_];     // W_out fp16
__device__ __align__(16) __half g_Hh[M_*H_];             // hs fp16 (written by scan)
__device__ __align__(16) float g_pre[M_*H_];   // x_t @ W_ih^T + b_ih + b_hh
__device__ __align__(16) float g_h  [2*B_*H_]; // double-buffered current h
__device__ float g_bsum[H_];
__device__ unsigned g_bar_count;

// ---------------- PTX helpers (arch-neutral: ldmatrix/mma/cp.async) --------
__device__ __forceinline__ uint32_t smem_to_u32(const void* p) {
    uint32_t a;
    asm("{ .reg .u64 t; cvta.to.shared.u64 t, %1; cvt.u32.u64 %0, t; }"
        : "=r"(a) : "l"(p));
    return a;
}
__device__ __forceinline__ void ldsm_x4(uint32_t* r, uint32_t addr) {
    asm volatile("ldmatrix.sync.aligned.m8n8.x4.shared.b16 {%0,%1,%2,%3}, [%4];"
        : "=r"(r[0]), "=r"(r[1]), "=r"(r[2]), "=r"(r[3]) : "r"(addr));
}
__device__ __forceinline__ void mma_f16(float* d, const uint32_t* a, const uint32_t* b) {
    asm volatile(
        "mma.sync.aligned.m16n8k16.row.col.f32.f16.f16.f32 "
        "{%0,%1,%2,%3}, {%4,%5,%6,%7}, {%8,%9}, {%0,%1,%2,%3};"
        : "+f"(d[0]), "+f"(d[1]), "+f"(d[2]), "+f"(d[3])
        : "r"(a[0]), "r"(a[1]), "r"(a[2]), "r"(a[3]), "r"(b[0]), "r"(b[1]));
}
__device__ __forceinline__ void cp16(uint32_t saddr, const void* g) {
    asm volatile("cp.async.cg.shared.global [%0], [%1], 16;" :: "r"(saddr), "l"(g));
}
#define CP_COMMIT() asm volatile("cp.async.commit_group;" ::: "memory")
#define CP_WAIT0()  asm volatile("cp.async.wait_group 0;" ::: "memory")
#define CP_WAIT1()  asm volatile("cp.async.wait_group 1;" ::: "memory")

// packed fp32x2 FMA (verified working on this toolchain)
__device__ __forceinline__ void ffma2(unsigned long long &c,
                                      unsigned long long a,
                                      unsigned long long b) {
    asm("fma.rn.f32x2 %0, %1, %2, %0;" : "+l"(c) : "l"(a), "l"(b));
}
__device__ __forceinline__ unsigned long long pk2(float x, float y) {
    float2 t; t.x = x; t.y = y;
    unsigned long long r; memcpy(&r, &t, 8); return r;
}
__device__ __forceinline__ float upk_sum(unsigned long long v) {
    float2 t; memcpy(&t, &v, 8); return t.x + t.y;
}

// ---------------- gather: emb rows split to fp16 hi/lo + fused bias --------
__global__ void gather_kernel(const int* __restrict__ x,
                              const float* __restrict__ embed,
                              const float* __restrict__ b_ih,
                              const float* __restrict__ b_hh) {
    int m = blockIdx.x;
    if (m < M_) {
        int tok = x[m];
        for (int i = threadIdx.x; i < H_; i += blockDim.x) {
            float v = embed[(size_t)tok * H_ + i];
            __half h = __float2half_rn(v);
            g_Ahi[(size_t)m * H_ + i] = h;
            g_Alo[(size_t)m * H_ + i] = __float2half_rn(v - __half2float(h));
        }
    } else {
        // also reset the scan's monotonic grid-barrier counter (stream order
        // guarantees this lands before scan_kernel starts, every replay)
        if (threadIdx.x == 0) g_bar_count = 0;
        for (int i = threadIdx.x; i < H_; i += blockDim.x)
            g_bsum[i] = b_ih[i] + b_hh[i];
    }
}

// ---------------- fp32 -> fp16 (round-to-nearest) --------------------------
__global__ void conv_h_kernel(const float* __restrict__ src,
                              __half* __restrict__ dst, size_t n) {
    size_t i = ((size_t)blockIdx.x * blockDim.x + threadIdx.x) * 4;
    if (i < n) {
        float4 v = *reinterpret_cast<const float4*>(src + i);
        __half2 a = {__float2half_rn(v.x), __float2half_rn(v.y)};
        __half2 b = {__float2half_rn(v.z), __float2half_rn(v.w)};
        *reinterpret_cast<__half2*>(dst + i)     = a;
        *reinterpret_cast<__half2*>(dst + i + 2) = b;
    }
}

// ---------------- fp16 HMMA GEMM, templated pass count ---------------------
// NPASS=2: C = (Ahi+Alo)*B + bias (A exact as fp16 pair)
// NPASS=1: C = Ahi*B + bias       (pure fp16 operands)
// A: [Mrows][H_] row-major, B: [Ncols][H_] row-major.  K = H_ = 1024 fixed.
#define GBM 128
#define GBN 128
#define GBK 32
#define NKC (H_/GBK)                    // 32 k-chunks
#define LDT 40                          // smem row stride in fp16 (pad 8)
#define MAT_B (GBM*LDT*2)               // 10240 bytes per matrix tile

template<int NPASS>
__global__ __launch_bounds__(256, 2)
void gemm_mma(const __half* __restrict__ Ahi, const __half* __restrict__ Alo,
              const __half* __restrict__ Bh,
              const float* __restrict__ bias, float* __restrict__ C, int Ndim) {
    constexpr int BSLOT   = NPASS;              // B tile slot index
    constexpr int STAGE_B = (NPASS + 1) * MAT_B;
    extern __shared__ __align__(16) char sm[];
    const uint32_t sb = smem_to_u32(sm);
    const int tid  = threadIdx.x;
    const int lane = tid & 31, wid = tid >> 5;
    const int wm = wid & 3, wn = wid >> 2;      // warp tile: rows 32*wm, cols 64*wn
    const int bm = blockIdx.x, bn = blockIdx.y;

    // ---- prefetch chunk c into stage c&1 ----
    auto prefetch = [&](int c) {
        const uint32_t st = sb + (uint32_t)(c & 1) * STAGE_B;
        const int kcol = c * GBK;
        #pragma unroll
        for (int q = 0; q < 2; q++) {
            const int u = tid + 256*q;
            const int r = u >> 2, sg = u & 3;
            const uint32_t so = (uint32_t)(r*LDT + sg*8) * 2;
            const size_t goA = (size_t)(bm*GBM + r) * H_ + kcol + sg*8;
            const size_t goB = (size_t)(bn*GBN + r) * H_ + kcol + sg*8;
            cp16(st + 0*MAT_B + so, Ahi + goA);
            if (NPASS == 2) cp16(st + 1*MAT_B + so, Alo + goA);
            cp16(st + BSLOT*MAT_B + so, Bh + goB);
        }
    };

    float acc[2][8][4];
    #pragma unroll
    for (int i = 0; i < 2; i++)
        #pragma unroll
        for (int j = 0; j < 8; j++)
            #pragma unroll
            for (int q = 0; q < 4; q++) acc[i][j][q] = 0.f;

    prefetch(0); CP_COMMIT();

    for (int c = 0; c < NKC; c++) {
        if (c + 1 < NKC) { prefetch(c + 1); CP_COMMIT(); CP_WAIT1(); }
        else             { CP_WAIT0(); }
        __syncthreads();

        const uint32_t st = sb + (uint32_t)(c & 1) * STAGE_B;
        #pragma unroll
        for (int ks = 0; ks < 2; ks++) {
            // A fragments: rows wm*32 + f*16 + lane%16
            uint32_t ah[8], al[8];
            #pragma unroll
            for (int f = 0; f < 2; f++) {
                const int row = wm*32 + f*16 + (lane & 15);
                const uint32_t off = (uint32_t)(row*LDT + ks*16 + (lane >> 4)*8) * 2;
                ldsm_x4(ah + 4*f, st + 0*MAT_B + off);
                if (NPASS == 2) ldsm_x4(al + 4*f, st + 1*MAT_B + off);
            }
            // B fragments
            uint32_t bb[16];
            #pragma unroll
            for (int p = 0; p < 4; p++) {
                const int n  = wn*64 + p*16 + ((lane >> 4) << 3) + (lane & 7);
                const int kc = ks*16 + ((lane >> 3) & 1) * 8;
                const uint32_t off = (uint32_t)(n*LDT + kc) * 2;
                ldsm_x4(bb + 4*p, st + BSLOT*MAT_B + off);
            }
            // pass 1: Ahi * B
            #pragma unroll
            for (int fm = 0; fm < 2; fm++)
                #pragma unroll
                for (int fn = 0; fn < 8; fn++)
                    mma_f16(acc[fm][fn], ah + 4*fm, bb + 2*fn);
            // pass 2: Alo * B
            if (NPASS == 2) {
                #pragma unroll
                for (int fm = 0; fm < 2; fm++)
                    #pragma unroll
                    for (int fn = 0; fn < 8; fn++)
                        mma_f16(acc[fm][fn], al + 4*fm, bb + 2*fn);
            }
        }
        __syncthreads();
    }

    // ---- epilogue: acc + bias -> C ----
    #pragma unroll
    for (int fm = 0; fm < 2; fm++) {
        const int row = bm*GBM + wm*32 + fm*16 + (lane >> 2);
        #pragma unroll
        for (int fn = 0; fn < 8; fn++) {
            const int col = bn*GBN + wn*64 + fn*8 + (lane & 3)*2;
            const float2 bv = *reinterpret_cast<const float2*>(bias + col);
            float2 o0, o1;
            o0.x = acc[fm][fn][0] + bv.x; o0.y = acc[fm][fn][1] + bv.y;
            o1.x = acc[fm][fn][2] + bv.x; o1.y = acc[fm][fn][3] + bv.y;
            *reinterpret_cast<float2*>(C + (size_t)row     * Ndim + col) = o0;
            *reinterpret_cast<float2*>(C + (size_t)(row+8) * Ndim + col) = o1;
        }
    }
}

// ---------------- persistent scan: 128 CTAs x 128 thr, 2 cols/warp ---------
// Grid barrier: monotonic counter, RED arrival, hot volatile poll, single
// release fence per CTA per step. h cross-step traffic is L1-bypassing
// (__stcg / __ldcg), so no acquire-side L1 invalidate is needed.
// Scan writes hidden states DIRECTLY as fp16 (g_Hh) — the output GEMM's A
// operand — eliminating the fp32 hs array and its conversion kernel.
#define SCAN_BLOCKS 128
#define SCAN_THREADS 128

__device__ __forceinline__ void grid_barrier_t(unsigned target) {
    __syncthreads();
    if (threadIdx.x == 0) {
        __threadfence();                       // release: publish h writes to L2
        atomicAdd(&g_bar_count, 1);            // result unused -> REDG
        const volatile unsigned* c = (const volatile unsigned*)&g_bar_count;
        while (*c < target) { }                // hot poll (L2)
    }
    __syncthreads();                            // exec+compiler barrier for CTA
}

__global__ __launch_bounds__(SCAN_THREADS)
void scan_kernel(const float* __restrict__ Whh, float* __restrict__ hfinal) {
    __shared__ __align__(16) float hsh[B_*H_];   // 32 KB
    const int tid  = threadIdx.x;
    const int warp = tid >> 5;                   // 0..3
    const int lane = tid & 31;
    const int j0   = blockIdx.x * 8 + warp * 2;  // two adjacent columns per warp
    const int j1   = j0 + 1;

    // Two W_hh rows stay in registers, packed as f32x2 pairs.
    unsigned long long w0[16], w1[16];
    {
        const float4* r0 = reinterpret_cast<const float4*>(Whh + (size_t)j0 * H_);
        const float4* r1 = reinterpret_cast<const float4*>(Whh + (size_t)j1 * H_);
        #pragma unroll
        for (int i = 0; i < 8; i++) {
            float4 a = r0[lane + 32*i];
            float4 b = r1[lane + 32*i];
            w0[2*i]   = pk2(a.x, a.y); w0[2*i+1] = pk2(a.z, a.w);
            w1[2*i]   = pk2(b.x, b.y); w1[2*i+1] = pk2(b.z, b.w);
        }
    }

    // zero h buffer 0 (L2-resident stores)
    {
        int idx = blockIdx.x*SCAN_THREADS + tid;
        if (idx < B_*H_) __stcg(&g_h[idx], 0.f);
    }
    unsigned bar_k = 1;
    grid_barrier_t(bar_k * SCAN_BLOCKS); bar_k++;

    for (int t = 0; t < T_; t++) {
        const int rp = t & 1, wp = rp ^ 1;
        // stage current h into shared, bypassing L1 (coherence point = L2)
        float4* hs4 = reinterpret_cast<float4*>(hsh);
        const float4* hg4 = reinterpret_cast<const float4*>(g_h + rp*B_*H_);
        #pragma unroll
        for (int i = 0; i < (B_*H_/4)/SCAN_THREADS; i++)
            hs4[tid + SCAN_THREADS*i] = __ldcg(&hg4[tid + SCAN_THREADS*i]);
        __syncthreads();

        unsigned long long a0[B_], a1[B_];
        #pragma unroll
        for (int b = 0; b < B_; b++) { a0[b] = 0ull; a1[b] = 0ull; }
        #pragma unroll
        for (int i = 0; i < 8; i++) {
            const unsigned long long wl0 = w0[2*i], wh0 = w0[2*i+1];
            const unsigned long long wl1 = w1[2*i], wh1 = w1[2*i+1];
            #pragma unroll
            for (int b = 0; b < B_; b++) {
                const float4 hv = *reinterpret_cast<const float4*>(&hsh[b*H_ + lane*4 + 128*i]);
                const unsigned long long hl = pk2(hv.x, hv.y);
                const unsigned long long hh = pk2(hv.z, hv.w);
                ffma2(a0[b], wl0, hl); ffma2(a0[b], wh0, hh);
                ffma2(a1[b], wl1, hl); ffma2(a1[b], wh1, hh);
            }
        }
        // butterfly-reduce both column accumulators (all lanes get results)
        float s0[B_], s1[B_];
        #pragma unroll
        for (int b = 0; b < B_; b++) {
            float v0 = upk_sum(a0[b]), v1 = upk_sum(a1[b]);
            #pragma unroll
            for (int off = 16; off; off >>= 1) {
                v0 += __shfl_xor_sync(0xffffffffu, v0, off);
                v1 += __shfl_xor_sync(0xffffffffu, v1, off);
            }
            s0[b] = v0; s1[b] = v1;
        }
        // lanes 0-7 write column j0 (batch=lane); lanes 8-15 write j1
        if (lane < 16) {
            const int b = lane & 7;
            float va = s0[0], vb = s1[0];
            if (b == 1) { va = s0[1]; vb = s1[1]; }
            if (b == 2) { va = s0[2]; vb = s1[2]; }
            if (b == 3) { va = s0[3]; vb = s1[3]; }
            if (b == 4) { va = s0[4]; vb = s1[4]; }
            if (b == 5) { va = s0[5]; vb = s1[5]; }
            if (b == 6) { va = s0[6]; vb = s1[6]; }
            if (b == 7) { va = s0[7]; vb = s1[7]; }
            const float a = (lane < 8) ? va : vb;
            const int   j = (lane < 8) ? j0 : j1;
            const float hn = tanhf(a + g_pre[(size_t)b*(T_*H_) + t*H_ + j]);
            __stcg(&g_h[wp*B_*H_ + b*H_ + j], hn);
            g_Hh[(size_t)b*(T_*H_) + t*H_ + j] = __float2half_rn(hn);
            if (t == T_-1) hfinal[b*H_ + j] = hn;
        }
        grid_barrier_t(bar_k * SCAN_BLOCKS); bar_k++;
    }
}

// ---------------- launch ----------------------------------------------------
extern "C" void kernel_launch(void* const* d_in, const int* in_sizes, int n_in,
                              void* d_out, int out_size) {
    const int*   x     = (const int*)  d_in[0];
    const float* embed = (const float*)d_in[1];
    const float* W_ih  = (const float*)d_in[2];
    const float* b_ih  = (const float*)d_in[3];
    const float* W_hh  = (const float*)d_in[4];
    const float* b_hh  = (const float*)d_in[5];
    const float* W_out = (const float*)d_in[6];
    const float* b_out = (const float*)d_in[7];
    float* out = (float*)d_out;

    void *p_Ahi, *p_Alo, *p_Wih, *p_Wo, *p_Hh, *p_pre, *p_bsum;
    cudaGetSymbolAddress(&p_Ahi, g_Ahi);   cudaGetSymbolAddress(&p_Alo, g_Alo);
    cudaGetSymbolAddress(&p_Wih, g_Wih);   cudaGetSymbolAddress(&p_Wo, g_Wo);
    cudaGetSymbolAddress(&p_Hh, g_Hh);
    cudaGetSymbolAddress(&p_pre, g_pre);   cudaGetSymbolAddress(&p_bsum, g_bsum);

    cudaFuncSetAttribute(gemm_mma<2>, cudaFuncAttributeMaxDynamicSharedMemorySize, 3*MAT_B*2);
    cudaFuncSetAttribute(gemm_mma<1>, cudaFuncAttributeMaxDynamicSharedMemorySize, 2*MAT_B*2);

    // 1) gather embeddings (split to fp16 hi/lo) + fused bias + barrier reset
    gather_kernel<<<M_ + 1, 256>>>(x, embed, b_ih, b_hh);

    // 2) convert weights to fp16
    conv_h_kernel<<<(H_*H_/4 + 255)/256, 256>>>(W_ih, (__half*)p_Wih, (size_t)H_*H_);
    conv_h_kernel<<<(int)(((size_t)V_*H_/4 + 255)/256), 256>>>(W_out, (__half*)p_Wo, (size_t)V_*H_);

    // 3) pre = emb @ W_ih^T + (b_ih + b_hh)   [2048 x 1024], exact-A 2-pass
    gemm_mma<2><<<dim3(M_/GBM, H_/GBN), 256, 3*MAT_B*2>>>(
        (const __half*)p_Ahi, (const __half*)p_Alo, (const __half*)p_Wih,
        (const float*)p_bsum, (float*)p_pre, H_);

    // 4) persistent recurrent scan; writes g_Hh (fp16) + h_final tail of d_out
    scan_kernel<<<SCAN_BLOCKS, SCAN_THREADS>>>(W_hh, out + (size_t)M_ * V_);

    // 5) outputs = hs @ W_out^T + b_out   [2048 x 32000], pure-fp16 1-pass
    gemm_mma<1><<<dim3(M_/GBM, V_/GBN), 256, 2*MAT_B*2>>>(
        (const __half*)p_Hh, (const __half*)nullptr, (const __half*)p_Wo,
        b_out, out, V_);
}